// round 2
// baseline (speedup 1.0000x reference)
#include <cuda_runtime.h>

#define N_PTS 8192
#define DIMS  128
#define TI    64
#define TJ    128
#define NTHR  256

__device__ float g_sq[N_PTS];
__device__ int   g_lab64;   // 1 if label buffer is int64-layout, 0 if int32

// Detect label dtype layout: int64 little-endian => odd int32 words all zero.
__global__ void detect_lab_kernel(const int* __restrict__ lab) {
    if (threadIdx.x == 0) {
        int all_zero = 1;
        #pragma unroll 8
        for (int i = 0; i < 256; ++i)
            if (lab[2 * i + 1] != 0) { all_zero = 0; break; }
        g_lab64 = all_zero;
    }
}

// One warp per row: squared L2 norms.
__global__ void sqnorm_kernel(const float* __restrict__ f) {
    int warp = threadIdx.x >> 5;
    int lane = threadIdx.x & 31;
    int row  = blockIdx.x * 8 + warp;
    if (row >= N_PTS) return;
    const float* p = f + (long)row * DIMS;
    float v0 = p[lane], v1 = p[lane + 32], v2 = p[lane + 64], v3 = p[lane + 96];
    float s = v0 * v0 + v1 * v1 + v2 * v2 + v3 * v3;
    #pragma unroll
    for (int m = 16; m; m >>= 1) s += __shfl_xor_sync(0xffffffffu, s, m);
    if (lane == 0) g_sq[row] = s;
}

// Fused pairwise-distance + hardest-pos/neg + loss kernel.
extern "C" __global__ void __launch_bounds__(NTHR, 1)
triplet_kernel(const float* __restrict__ f,
               const int* __restrict__ lab,
               float* __restrict__ out) {
    extern __shared__ float smem[];
    float* Fi  = smem;                       // [DIMS][TI]  transposed
    float* Fj  = smem + DIMS * TI;           // [DIMS][TJ]  transposed
    float* SQJ = Fj + DIMS * TJ;             // [TJ]
    int*   LJ  = (int*)(SQJ + TJ);           // [TJ]
    float* RED = (float*)(LJ + TJ);          // [16]

    const int t  = threadIdx.x;
    const int tx = t & 15;          // j group
    const int ty = t >> 4;          // i group
    const int i0 = blockIdx.x * TI;
    const int l64 = g_lab64;

    // ---- load Fi tile transposed: Fi[k][i] ----
    #pragma unroll
    for (int u = 0; u < 8; ++u) {
        int idx = t + u * NTHR;          // float4 index, 0..2047
        int row = idx >> 5;              // 0..63
        int k4  = idx & 31;              // 0..31
        float4 v = ((const float4*)(f + (long)(i0 + row) * DIMS))[k4];
        int k = k4 * 4;
        Fi[(k + 0) * TI + row] = v.x;
        Fi[(k + 1) * TI + row] = v.y;
        Fi[(k + 2) * TI + row] = v.z;
        Fi[(k + 3) * TI + row] = v.w;
    }

    const int ibase = i0 + ty * 4;
    int   li[4];
    float sqi[4];
    #pragma unroll
    for (int r = 0; r < 4; ++r) {
        int gi = ibase + r;
        li[r]  = lab[l64 ? (gi << 1) : gi];
        sqi[r] = g_sq[gi];
    }

    float ap[4], an[4];
    #pragma unroll
    for (int r = 0; r < 4; ++r) { ap[r] = -1e30f; an[r] = 1e30f; }

    for (int jt = 0; jt < N_PTS / TJ; ++jt) {
        const int j0 = jt * TJ;
        __syncthreads();   // previous tile fully consumed

        // ---- load Fj tile transposed: Fj[k][j] ----
        #pragma unroll
        for (int u = 0; u < 16; ++u) {
            int idx = t + u * NTHR;       // float4 index, 0..4095
            int row = idx >> 5;           // 0..127
            int k4  = idx & 31;
            float4 v = ((const float4*)(f + (long)(j0 + row) * DIMS))[k4];
            int k = k4 * 4;
            Fj[(k + 0) * TJ + row] = v.x;
            Fj[(k + 1) * TJ + row] = v.y;
            Fj[(k + 2) * TJ + row] = v.z;
            Fj[(k + 3) * TJ + row] = v.w;
        }
        if (t < TJ) {
            int gj = j0 + t;
            LJ[t]  = lab[l64 ? (gj << 1) : gj];
            SQJ[t] = g_sq[gj];
        }
        __syncthreads();

        // ---- 4x8 register-tile dot products over k ----
        float acc[4][8];
        #pragma unroll
        for (int r = 0; r < 4; ++r)
            #pragma unroll
            for (int c = 0; c < 8; ++c) acc[r][c] = 0.f;

        #pragma unroll 4
        for (int k = 0; k < DIMS; ++k) {
            float4 a4 = *(const float4*)&Fi[k * TI + ty * 4];
            float4 b0 = *(const float4*)&Fj[k * TJ + tx * 8];
            float4 b1 = *(const float4*)&Fj[k * TJ + tx * 8 + 4];
            float a[4] = {a4.x, a4.y, a4.z, a4.w};
            float b[8] = {b0.x, b0.y, b0.z, b0.w, b1.x, b1.y, b1.z, b1.w};
            #pragma unroll
            for (int r = 0; r < 4; ++r)
                #pragma unroll
                for (int c = 0; c < 8; ++c)
                    acc[r][c] = fmaf(a[r], b[c], acc[r][c]);
        }

        // ---- epilogue: masked max/min on d2 ----
        #pragma unroll
        for (int c = 0; c < 8; ++c) {
            const int jcol = tx * 8 + c;
            const int jg   = j0 + jcol;
            const int ljc  = LJ[jcol];
            const float sj = SQJ[jcol];
            #pragma unroll
            for (int r = 0; r < 4; ++r) {
                float d2 = fmaf(-2.f, acc[r][c], sqi[r] + sj);
                if (li[r] == ljc) {
                    if (ibase + r != jg) ap[r] = fmaxf(ap[r], d2);
                } else {
                    an[r] = fminf(an[r], d2);
                }
            }
        }
    }

    // ---- reduce across the 16 tx lanes sharing the same i-rows ----
    #pragma unroll
    for (int m = 1; m < 16; m <<= 1) {
        #pragma unroll
        for (int r = 0; r < 4; ++r) {
            ap[r] = fmaxf(ap[r], __shfl_xor_sync(0xffffffffu, ap[r], m));
            an[r] = fminf(an[r], __shfl_xor_sync(0xffffffffu, an[r], m));
        }
    }

    if (tx == 0) {
        float s = 0.f;
        #pragma unroll
        for (int r = 0; r < 4; ++r) {
            float dap = (ap[r] > -1e29f) ? sqrtf(fmaxf(ap[r], 0.f)) : 0.f;
            float dan = (an[r] <  1e29f) ? sqrtf(fmaxf(an[r], 0.f)) : 1e6f;
            s += fmaxf(0.f, 0.3f - (dan - dap));
        }
        RED[ty] = s;
    }
    __syncthreads();
    if (t == 0) {
        float tot = 0.f;
        #pragma unroll
        for (int g = 0; g < 16; ++g) tot += RED[g];
        atomicAdd(out, tot * (1.0f / (float)N_PTS));
    }
}

extern "C" void kernel_launch(void* const* d_in, const int* in_sizes, int n_in,
                              void* d_out, int out_size) {
    const float* feat = (const float*)d_in[0];
    const int*   lab  = (const int*)d_in[1];
    float*       out  = (float*)d_out;
    (void)in_sizes; (void)n_in; (void)out_size;

    const int smem_bytes = (DIMS * TI + DIMS * TJ + TJ) * 4 + TJ * 4 + 16 * 4;
    cudaFuncSetAttribute(triplet_kernel,
                         cudaFuncAttributeMaxDynamicSharedMemorySize,
                         smem_bytes);

    cudaMemsetAsync(d_out, 0, sizeof(float));
    detect_lab_kernel<<<1, 32>>>(lab);
    sqnorm_kernel<<<N_PTS / 8, 256>>>(feat);
    triplet_kernel<<<N_PTS / TI, NTHR, smem_bytes>>>(feat, lab, out);
}

// round 4
// speedup vs baseline: 8.7913x; 8.7913x over previous
#include <cuda_runtime.h>
#include <cstdint>

#define NP 8192
#define DK 128
#define NTJ 32      // j-tiles per CTA (half of 64)
#define NTHR 256

__device__ float    g_afrag[NP * DK];   // A-fragment-ordered tf32 features
__device__ float    g_bfrag[NP * DK];   // B-fragment-ordered tf32 features
__device__ float2   g_meta[NP];         // (sq_norm, label as float)
__device__ unsigned g_ap[NP];
__device__ unsigned g_an[NP];
__device__ int      g_lab64;

// ---------- helpers ----------
__device__ __forceinline__ uint32_t smem_u32(const void* p) {
    uint32_t a;
    asm("{ .reg .u64 t; cvta.to.shared.u64 t, %1; cvt.u32.u64 %0, t; }"
        : "=r"(a) : "l"(p));
    return a;
}
__device__ __forceinline__ void cp16(uint32_t dst, const void* src) {
    asm volatile("cp.async.cg.shared.global [%0], [%1], 16;" :: "r"(dst), "l"(src));
}
__device__ __forceinline__ void cp8(uint32_t dst, const void* src) {
    asm volatile("cp.async.ca.shared.global [%0], [%1], 8;" :: "r"(dst), "l"(src));
}
#define CP_COMMIT() asm volatile("cp.async.commit_group;" ::: "memory")

__device__ __forceinline__ void mma_tf32(float* d, const float4& a, const float2& b) {
    asm volatile(
        "mma.sync.aligned.m16n8k8.row.col.f32.tf32.tf32.f32 "
        "{%0,%1,%2,%3}, {%4,%5,%6,%7}, {%8,%9}, {%0,%1,%2,%3};"
        : "+f"(d[0]), "+f"(d[1]), "+f"(d[2]), "+f"(d[3])
        : "r"(__float_as_uint(a.x)), "r"(__float_as_uint(a.y)),
          "r"(__float_as_uint(a.z)), "r"(__float_as_uint(a.w)),
          "r"(__float_as_uint(b.x)), "r"(__float_as_uint(b.y)));
}

// ---------- small kernels ----------
__global__ void detect_lab_kernel(const int* __restrict__ lab) {
    if (threadIdx.x == 0) {
        int all_zero = 1;
        for (int i = 0; i < 256; ++i)
            if (lab[2 * i + 1] != 0) { all_zero = 0; break; }
        g_lab64 = all_zero;
    }
}

__global__ void init_kernel() {
    int i = blockIdx.x * 256 + threadIdx.x;
    g_ap[i] = 0u;
    g_an[i] = __float_as_uint(1e12f);
}

// One warp per row: tf32-round features into frag-ordered global copies,
// exact fp32 sq-norms + label into g_meta.
__global__ void prep_kernel(const float* __restrict__ f,
                            const int* __restrict__ lab) {
    int warp = threadIdx.x >> 5, lane = threadIdx.x & 31;
    int row  = blockIdx.x * 8 + warp;
    const float* p = f + (size_t)row * DK;
    const int l64 = g_lab64;

    const int tile = row >> 7;         // 128-row tile
    const int n    = row & 127;        // row within tile
    float* abase = g_afrag + (size_t)tile * (128 * DK);
    float* bbase = g_bfrag + (size_t)tile * (128 * DK);

    // A-frag layout constants (m16n8k8 A fragment, warps 2x4, mfrag 4)
    const int warp_m = n >> 6, mfrag = (n >> 4) & 3, r16 = n & 15;
    const int a_base = warp_m * 8192 + mfrag * 128 + (r16 & 7) * 16 + (r16 >> 3);
    // B-frag layout constants (B fragment, warp_n 4, nfrag 4)
    const int warp_n = n >> 5, nfrag = (n >> 3) & 3;
    const int b_base = warp_n * 4096 + nfrag * 64 + (n & 7) * 8;

    float s = 0.f;
    #pragma unroll
    for (int q = 0; q < 4; ++q) {
        int k = lane + q * 32;
        float v = p[k];
        s += v * v;
        uint32_t tv;
        asm("cvt.rna.tf32.f32 %0, %1;" : "=r"(tv) : "f"(v));
        float vt = __uint_as_float(tv);
        int ks = k >> 3, c = k & 7;
        abase[a_base + ks * 512 + (c & 3) * 4 + (c >> 2) * 2] = vt;
        bbase[b_base + ks * 256 + (c & 3) * 2 + (c >> 2)]     = vt;
    }
    #pragma unroll
    for (int m = 16; m; m >>= 1) s += __shfl_xor_sync(0xffffffffu, s, m);
    if (lane == 0)
        g_meta[row] = make_float2(s, (float)lab[l64 ? (row << 1) : row]);
}

__global__ void loss_kernel(float* __restrict__ out) {
    __shared__ float red[256];
    int t = threadIdx.x;
    int i = blockIdx.x * 256 + t;
    float ap = __uint_as_float(g_ap[i]);
    float an = __uint_as_float(g_an[i]);
    float dap = sqrtf(ap);
    float dan = (an > 9e11f) ? 1e6f : sqrtf(an);
    red[t] = fmaxf(0.f, 0.3f - (dan - dap));
    __syncthreads();
    #pragma unroll
    for (int s = 128; s; s >>= 1) {
        if (t < s) red[t] += red[t + s];
        __syncthreads();
    }
    if (t == 0) atomicAdd(out, red[0] * (1.0f / (float)NP));
}

// ---------- main fused tf32-MMA kernel ----------
// grid = 64 i-tiles x 2 j-halves, 256 threads (8 warps, 2x4 warp grid).
// Per CTA: D(128 x 4096) = Ai . Bj^T, accumulators in registers,
// epilogue fused (masked hardest-pos max / hardest-neg min of d2).
__global__ void __launch_bounds__(NTHR, 1)
triplet_mma(void) {
    extern __shared__ float smem[];
    float*  sA = smem;                       // 16384 f (64KB)
    float*  sB = smem + 16384;               // 2 x 16384 f
    float2* sM = (float2*)(smem + 16384 * 3);// 2 x 128 float2
    const uint32_t sBu = smem_u32(sB);
    const uint32_t sMu = smem_u32(sM);

    const int t = threadIdx.x, lane = t & 31, wid = t >> 5;
    const int warp_m = wid >> 2, warp_n = wid & 3;
    const int itile = blockIdx.x >> 1, jh = blockIdx.x & 1;
    const int i0  = itile * 128;
    const int jt0 = jh * NTJ;

    // prologue: A tile + B tile 0 + meta 0 (all contiguous 16B cp.async)
    {
        const float4* as = (const float4*)(g_afrag + (size_t)itile * 16384);
        uint32_t ad = smem_u32(sA);
        #pragma unroll
        for (int u = 0; u < 16; ++u)
            cp16(ad + (t + u * 256) * 16, as + t + u * 256);
        const float4* bs = (const float4*)(g_bfrag + (size_t)jt0 * 16384);
        #pragma unroll
        for (int u = 0; u < 16; ++u)
            cp16(sBu + (t + u * 256) * 16, bs + t + u * 256);
        if (t < 128) cp8(sMu + t * 8, &g_meta[jt0 * 128 + t]);
        CP_COMMIT();
    }

    // row metadata (8 rows per thread)
    float rsq[8], rlab[8];
    #pragma unroll
    for (int mf = 0; mf < 4; ++mf)
        #pragma unroll
        for (int rr = 0; rr < 2; ++rr) {
            float2 m = g_meta[i0 + warp_m * 64 + mf * 16 + rr * 8 + (lane >> 2)];
            rsq[mf * 2 + rr]  = m.x;
            rlab[mf * 2 + rr] = m.y;
        }

    float ap[8], an[8];
    #pragma unroll
    for (int r = 0; r < 8; ++r) { ap[r] = 0.f; an[r] = 1e12f; }

    for (int jt = 0; jt < NTJ; ++jt) {
        const int buf = jt & 1;
        // prefetch next tile into other buffer
        if (jt + 1 < NTJ) {
            const float4* bs =
                (const float4*)(g_bfrag + (size_t)(jt0 + jt + 1) * 16384);
            uint32_t bd = sBu + (uint32_t)(buf ^ 1) * 65536u;
            #pragma unroll
            for (int u = 0; u < 16; ++u)
                cp16(bd + (t + u * 256) * 16, bs + t + u * 256);
            if (t < 128)
                cp8(sMu + (buf ^ 1) * 1024 + t * 8,
                    &g_meta[(jt0 + jt + 1) * 128 + t]);
            CP_COMMIT();
            asm volatile("cp.async.wait_group 1;" ::: "memory");
        } else {
            asm volatile("cp.async.wait_group 0;" ::: "memory");
        }
        __syncthreads();

        // ---- MMA over K=128 (16 k-steps) ----
        float acc[4][4][4];
        #pragma unroll
        for (int mf = 0; mf < 4; ++mf)
            #pragma unroll
            for (int nf = 0; nf < 4; ++nf)
                #pragma unroll
                for (int e = 0; e < 4; ++e) acc[mf][nf][e] = 0.f;

        const float4* Af = (const float4*)(sA + warp_m * 8192);
        const float2* Bf = (const float2*)(sB + buf * 16384 + warp_n * 4096);
        #pragma unroll
        for (int ks = 0; ks < 16; ++ks) {
            float4 a[4]; float2 b[4];
            #pragma unroll
            for (int mf = 0; mf < 4; ++mf) a[mf] = Af[ks * 128 + mf * 32 + lane];
            #pragma unroll
            for (int nf = 0; nf < 4; ++nf) b[nf] = Bf[ks * 128 + nf * 32 + lane];
            #pragma unroll
            for (int mf = 0; mf < 4; ++mf)
                #pragma unroll
                for (int nf = 0; nf < 4; ++nf)
                    mma_tf32(acc[mf][nf], a[mf], b[nf]);
        }

        // ---- fused epilogue ----
        const float2* M = sM + buf * 128;
        const int jg0 = (jt0 + jt) * 128;
        const bool dia = (jg0 == i0);
        #pragma unroll
        for (int nf = 0; nf < 4; ++nf) {
            const int cl = warp_n * 32 + nf * 8 + (lane & 3) * 2;
            const float2 m0 = M[cl];
            const float2 m1 = M[cl + 1];
            #pragma unroll
            for (int mf = 0; mf < 4; ++mf)
                #pragma unroll
                for (int rr = 0; rr < 2; ++rr) {
                    const int r = mf * 2 + rr;
                    float d20 = fmaf(-2.f, acc[mf][nf][rr * 2 + 0], rsq[r] + m0.x);
                    float d21 = fmaf(-2.f, acc[mf][nf][rr * 2 + 1], rsq[r] + m1.x);
                    if (!dia) {
                        if (rlab[r] == m0.y) ap[r] = fmaxf(ap[r], d20);
                        else                 an[r] = fminf(an[r], d20);
                        if (rlab[r] == m1.y) ap[r] = fmaxf(ap[r], d21);
                        else                 an[r] = fminf(an[r], d21);
                    } else {
                        int gi = i0 + warp_m * 64 + mf * 16 + rr * 8 + (lane >> 2);
                        int gj = jg0 + cl;
                        if (rlab[r] == m0.y) {
                            if (gi != gj) ap[r] = fmaxf(ap[r], d20);
                        } else an[r] = fminf(an[r], d20);
                        if (rlab[r] == m1.y) {
                            if (gi != gj + 1) ap[r] = fmaxf(ap[r], d21);
                        } else an[r] = fminf(an[r], d21);
                    }
                }
        }
        __syncthreads();
    }

    // reduce over the 4 lanes sharing the same rows (lane%4 group)
    #pragma unroll
    for (int r = 0; r < 8; ++r) {
        ap[r] = fmaxf(ap[r], __shfl_xor_sync(0xffffffffu, ap[r], 1));
        ap[r] = fmaxf(ap[r], __shfl_xor_sync(0xffffffffu, ap[r], 2));
        an[r] = fminf(an[r], __shfl_xor_sync(0xffffffffu, an[r], 1));
        an[r] = fminf(an[r], __shfl_xor_sync(0xffffffffu, an[r], 2));
    }
    if ((lane & 3) == 0) {
        #pragma unroll
        for (int r = 0; r < 8; ++r) {
            int row = i0 + warp_m * 64 + (r >> 1) * 16 + (r & 1) * 8 + (lane >> 2);
            atomicMax(&g_ap[row], __float_as_uint(fmaxf(ap[r], 0.f)));
            atomicMin(&g_an[row], __float_as_uint(fmaxf(an[r], 0.f)));
        }
    }
}

// ---------- launch ----------
extern "C" void kernel_launch(void* const* d_in, const int* in_sizes, int n_in,
                              void* d_out, int out_size) {
    const float* feat = (const float*)d_in[0];
    const int*   lab  = (const int*)d_in[1];
    float*       out  = (float*)d_out;
    (void)in_sizes; (void)n_in; (void)out_size;

    const int smem_bytes = (16384 * 3 + 256 * 2) * 4;   // 198656
    cudaFuncSetAttribute(triplet_mma,
                         cudaFuncAttributeMaxDynamicSharedMemorySize,
                         smem_bytes);

    cudaMemsetAsync(d_out, 0, sizeof(float));
    detect_lab_kernel<<<1, 32>>>(lab);
    init_kernel<<<NP / 256, 256>>>();
    prep_kernel<<<NP / 8, 256>>>(feat, lab);
    triplet_mma<<<(NP / 128) * 2, NTHR, smem_bytes>>>();
    loss_kernel<<<NP / 256, 256>>>(out);
}

// round 5
// speedup vs baseline: 9.0912x; 1.0341x over previous
#include <cuda_runtime.h>
#include <cstdint>

#define NP 8192
#define DK 128
#define NTJ 32      // j-tiles per CTA (half of 64)
#define NTHR 512

__device__ float    g_afrag[NP * DK];   // A-fragment-ordered tf32 features
__device__ float    g_bfrag[NP * DK];   // B-fragment-ordered tf32 features
__device__ float2   g_meta[NP];         // (sq_norm, label as float)
__device__ unsigned g_ap[NP];
__device__ unsigned g_an[NP];
__device__ int      g_lab64;

// ---------- helpers ----------
__device__ __forceinline__ uint32_t smem_u32(const void* p) {
    uint32_t a;
    asm("{ .reg .u64 t; cvta.to.shared.u64 t, %1; cvt.u32.u64 %0, t; }"
        : "=r"(a) : "l"(p));
    return a;
}
__device__ __forceinline__ void cp16(uint32_t dst, const void* src) {
    asm volatile("cp.async.cg.shared.global [%0], [%1], 16;" :: "r"(dst), "l"(src));
}
__device__ __forceinline__ void cp8(uint32_t dst, const void* src) {
    asm volatile("cp.async.ca.shared.global [%0], [%1], 8;" :: "r"(dst), "l"(src));
}
#define CP_COMMIT() asm volatile("cp.async.commit_group;" ::: "memory")

__device__ __forceinline__ void mma_tf32(float* d, const float4& a, const float2& b) {
    asm volatile(
        "mma.sync.aligned.m16n8k8.row.col.f32.tf32.tf32.f32 "
        "{%0,%1,%2,%3}, {%4,%5,%6,%7}, {%8,%9}, {%0,%1,%2,%3};"
        : "+f"(d[0]), "+f"(d[1]), "+f"(d[2]), "+f"(d[3])
        : "r"(__float_as_uint(a.x)), "r"(__float_as_uint(a.y)),
          "r"(__float_as_uint(a.z)), "r"(__float_as_uint(a.w)),
          "r"(__float_as_uint(b.x)), "r"(__float_as_uint(b.y)));
}

// ---------- small kernels ----------
__global__ void detect_lab_kernel(const int* __restrict__ lab) {
    if (threadIdx.x == 0) {
        int all_zero = 1;
        for (int i = 0; i < 256; ++i)
            if (lab[2 * i + 1] != 0) { all_zero = 0; break; }
        g_lab64 = all_zero;
    }
}

// One warp per row: tf32-round features into frag-ordered global copies,
// exact fp32 sq-norms + label into g_meta; also init ap/an.
__global__ void prep_kernel(const float* __restrict__ f,
                            const int* __restrict__ lab) {
    int warp = threadIdx.x >> 5, lane = threadIdx.x & 31;
    int row  = blockIdx.x * 8 + warp;
    const float* p = f + (size_t)row * DK;
    const int l64 = g_lab64;

    const int tile = row >> 7;         // 128-row tile
    const int n    = row & 127;        // row within tile

    float* abase = g_afrag + (size_t)tile * (128 * DK);
    float* bbase = g_bfrag + (size_t)tile * (128 * DK);

    // A-frag layout (warp grid 4x4: warp_m = n>>5, mfrag = (n>>4)&1)
    const int warp_m = n >> 5, mfrag = (n >> 4) & 1, r16 = n & 15;
    const int a_base = warp_m * 4096 + mfrag * 128 + (r16 & 7) * 16 + (r16 >> 3);
    // B-frag layout (warp_n = n>>5, nfrag = (n>>3)&3)
    const int warp_n = n >> 5, nfrag = (n >> 3) & 3;
    const int b_base = warp_n * 4096 + nfrag * 64 + (n & 7) * 8;

    float s = 0.f;
    #pragma unroll
    for (int q = 0; q < 4; ++q) {
        int k = lane + q * 32;
        float v = p[k];
        s += v * v;
        uint32_t tv;
        asm("cvt.rna.tf32.f32 %0, %1;" : "=r"(tv) : "f"(v));
        float vt = __uint_as_float(tv);
        int ks = k >> 3, c = k & 7;
        abase[a_base + ks * 256 + (c & 3) * 4 + (c >> 2) * 2] = vt;
        bbase[b_base + ks * 256 + (c & 3) * 2 + (c >> 2)]     = vt;
    }
    #pragma unroll
    for (int m = 16; m; m >>= 1) s += __shfl_xor_sync(0xffffffffu, s, m);
    if (lane == 0) {
        g_meta[row] = make_float2(s, (float)lab[l64 ? (row << 1) : row]);
        g_ap[row] = 0u;
        g_an[row] = __float_as_uint(1e12f);
    }
}

__global__ void loss_kernel(float* __restrict__ out) {
    __shared__ float red[256];
    int t = threadIdx.x;
    int i = blockIdx.x * 256 + t;
    float ap = __uint_as_float(g_ap[i]);
    float an = __uint_as_float(g_an[i]);
    float dap = sqrtf(ap);
    float dan = (an > 9e11f) ? 1e6f : sqrtf(an);
    red[t] = fmaxf(0.f, 0.3f - (dan - dap));
    __syncthreads();
    #pragma unroll
    for (int s = 128; s; s >>= 1) {
        if (t < s) red[t] += red[t + s];
        __syncthreads();
    }
    if (t == 0) atomicAdd(out, red[0] * (1.0f / (float)NP));
}

// ---------- main fused tf32-MMA kernel ----------
// grid = 64 i-tiles x 2 j-halves, 512 threads (16 warps, 4x4 warp grid).
// Each warp: 32 i-rows (2 m-frags) x 32 j-cols (4 n-frags).
__global__ void __launch_bounds__(NTHR, 1)
triplet_mma(void) {
    extern __shared__ float smem[];
    float*  sA = smem;                       // 16384 f (64KB)
    float*  sB = smem + 16384;               // 2 x 16384 f
    float2* sM = (float2*)(smem + 16384 * 3);// 2 x 128 float2
    const uint32_t sBu = smem_u32(sB);
    const uint32_t sMu = smem_u32(sM);

    const int t = threadIdx.x, lane = t & 31, wid = t >> 5;
    const int warp_m = wid >> 2, warp_n = wid & 3;
    const int itile = blockIdx.x >> 1, jh = blockIdx.x & 1;
    const int i0  = itile * 128;
    const int jt0 = jh * NTJ;

    // prologue: A tile + B tile 0 + meta 0
    {
        const float4* as = (const float4*)(g_afrag + (size_t)itile * 16384);
        uint32_t ad = smem_u32(sA);
        #pragma unroll
        for (int u = 0; u < 8; ++u)
            cp16(ad + (t + u * 512) * 16, as + t + u * 512);
        const float4* bs = (const float4*)(g_bfrag + (size_t)jt0 * 16384);
        #pragma unroll
        for (int u = 0; u < 8; ++u)
            cp16(sBu + (t + u * 512) * 16, bs + t + u * 512);
        if (t < 128) cp8(sMu + t * 8, &g_meta[jt0 * 128 + t]);
        CP_COMMIT();
    }

    // row metadata (4 rows per thread: mf 2 x rr 2)
    float rsq[4], rlab[4];
    #pragma unroll
    for (int mf = 0; mf < 2; ++mf)
        #pragma unroll
        for (int rr = 0; rr < 2; ++rr) {
            float2 m = g_meta[i0 + warp_m * 32 + mf * 16 + rr * 8 + (lane >> 2)];
            rsq[mf * 2 + rr]  = m.x;
            rlab[mf * 2 + rr] = m.y;
        }

    float ap[4], an[4];
    #pragma unroll
    for (int r = 0; r < 4; ++r) { ap[r] = 0.f; an[r] = 1e12f; }

    for (int jt = 0; jt < NTJ; ++jt) {
        const int buf = jt & 1;
        // prefetch next tile into other buffer
        if (jt + 1 < NTJ) {
            const float4* bs =
                (const float4*)(g_bfrag + (size_t)(jt0 + jt + 1) * 16384);
            uint32_t bd = sBu + (uint32_t)(buf ^ 1) * 65536u;
            #pragma unroll
            for (int u = 0; u < 8; ++u)
                cp16(bd + (t + u * 512) * 16, bs + t + u * 512);
            if (t < 128)
                cp8(sMu + (buf ^ 1) * 1024 + t * 8,
                    &g_meta[(jt0 + jt + 1) * 128 + t]);
            CP_COMMIT();
            asm volatile("cp.async.wait_group 1;" ::: "memory");
        } else {
            asm volatile("cp.async.wait_group 0;" ::: "memory");
        }
        __syncthreads();

        // ---- MMA over K=128 (16 k-steps), 2 m-frags x 4 n-frags ----
        float acc[2][4][4];
        #pragma unroll
        for (int mf = 0; mf < 2; ++mf)
            #pragma unroll
            for (int nf = 0; nf < 4; ++nf)
                #pragma unroll
                for (int e = 0; e < 4; ++e) acc[mf][nf][e] = 0.f;

        const float4* Af = (const float4*)(sA + warp_m * 4096);
        const float2* Bf = (const float2*)(sB + buf * 16384 + warp_n * 4096);
        #pragma unroll
        for (int ks = 0; ks < 16; ++ks) {
            float4 a[2]; float2 b[4];
            #pragma unroll
            for (int mf = 0; mf < 2; ++mf) a[mf] = Af[ks * 64 + mf * 32 + lane];
            #pragma unroll
            for (int nf = 0; nf < 4; ++nf) b[nf] = Bf[ks * 128 + nf * 32 + lane];
            #pragma unroll
            for (int mf = 0; mf < 2; ++mf)
                #pragma unroll
                for (int nf = 0; nf < 4; ++nf)
                    mma_tf32(acc[mf][nf], a[mf], b[nf]);
        }

        // ---- fused epilogue ----
        const float2* M = sM + buf * 128;
        const int jg0 = (jt0 + jt) * 128;
        const bool dia = (jg0 == i0);
        #pragma unroll
        for (int nf = 0; nf < 4; ++nf) {
            const int cl = warp_n * 32 + nf * 8 + (lane & 3) * 2;
            const float2 m0 = M[cl];
            const float2 m1 = M[cl + 1];
            #pragma unroll
            for (int mf = 0; mf < 2; ++mf)
                #pragma unroll
                for (int rr = 0; rr < 2; ++rr) {
                    const int r = mf * 2 + rr;
                    float d20 = fmaf(-2.f, acc[mf][nf][rr * 2 + 0], rsq[r] + m0.x);
                    float d21 = fmaf(-2.f, acc[mf][nf][rr * 2 + 1], rsq[r] + m1.x);
                    if (!dia) {
                        if (rlab[r] == m0.y) ap[r] = fmaxf(ap[r], d20);
                        else                 an[r] = fminf(an[r], d20);
                        if (rlab[r] == m1.y) ap[r] = fmaxf(ap[r], d21);
                        else                 an[r] = fminf(an[r], d21);
                    } else {
                        int gi = i0 + warp_m * 32 + mf * 16 + rr * 8 + (lane >> 2);
                        int gj = jg0 + cl;
                        if (rlab[r] == m0.y) {
                            if (gi != gj) ap[r] = fmaxf(ap[r], d20);
                        } else an[r] = fminf(an[r], d20);
                        if (rlab[r] == m1.y) {
                            if (gi != gj + 1) ap[r] = fmaxf(ap[r], d21);
                        } else an[r] = fminf(an[r], d21);
                    }
                }
        }
        __syncthreads();
    }

    // reduce over the 4 lanes sharing the same rows (lane%4 group)
    #pragma unroll
    for (int r = 0; r < 4; ++r) {
        ap[r] = fmaxf(ap[r], __shfl_xor_sync(0xffffffffu, ap[r], 1));
        ap[r] = fmaxf(ap[r], __shfl_xor_sync(0xffffffffu, ap[r], 2));
        an[r] = fminf(an[r], __shfl_xor_sync(0xffffffffu, an[r], 1));
        an[r] = fminf(an[r], __shfl_xor_sync(0xffffffffu, an[r], 2));
    }
    if ((lane & 3) == 0) {
        #pragma unroll
        for (int r = 0; r < 4; ++r) {
            int row = i0 + warp_m * 32 + (r >> 1) * 16 + (r & 1) * 8 + (lane >> 2);
            atomicMax(&g_ap[row], __float_as_uint(fmaxf(ap[r], 0.f)));
            atomicMin(&g_an[row], __float_as_uint(fmaxf(an[r], 0.f)));
        }
    }
}

// ---------- launch ----------
extern "C" void kernel_launch(void* const* d_in, const int* in_sizes, int n_in,
                              void* d_out, int out_size) {
    const float* feat = (const float*)d_in[0];
    const int*   lab  = (const int*)d_in[1];
    float*       out  = (float*)d_out;
    (void)in_sizes; (void)n_in; (void)out_size;

    const int smem_bytes = (16384 * 3 + 256 * 2) * 4;   // 198656
    cudaFuncSetAttribute(triplet_mma,
                         cudaFuncAttributeMaxDynamicSharedMemorySize,
                         smem_bytes);

    cudaMemsetAsync(d_out, 0, sizeof(float));
    detect_lab_kernel<<<1, 32>>>(lab);
    prep_kernel<<<NP / 8, 256>>>(feat, lab);
    triplet_mma<<<(NP / 128) * 2, NTHR, smem_bytes>>>();
    loss_kernel<<<NP / 256, 256>>>(out);
}

// round 6
// speedup vs baseline: 13.1676x; 1.4484x over previous
#include <cuda_runtime.h>
#include <cuda_fp16.h>
#include <cstdint>

#define NP 8192
#define DK 128
#define NTJ 32      // j-tiles per CTA (half of 64)
#define NTHR 512

__device__ __half   g_afrag[NP * DK];   // A-fragment-ordered fp16 features
__device__ __half   g_bfrag[NP * DK];   // B-fragment-ordered fp16 features
__device__ float2   g_meta[NP];         // (sq_norm, label as float)
__device__ unsigned g_ap[NP];
__device__ unsigned g_an[NP];
__device__ int      g_lab64;

// ---------- helpers ----------
__device__ __forceinline__ uint32_t smem_u32(const void* p) {
    uint32_t a;
    asm("{ .reg .u64 t; cvta.to.shared.u64 t, %1; cvt.u32.u64 %0, t; }"
        : "=r"(a) : "l"(p));
    return a;
}
__device__ __forceinline__ void cp16(uint32_t dst, const void* src) {
    asm volatile("cp.async.cg.shared.global [%0], [%1], 16;" :: "r"(dst), "l"(src));
}
__device__ __forceinline__ void cp8(uint32_t dst, const void* src) {
    asm volatile("cp.async.ca.shared.global [%0], [%1], 8;" :: "r"(dst), "l"(src));
}
#define CP_COMMIT() asm volatile("cp.async.commit_group;" ::: "memory")

__device__ __forceinline__ void mma_f16(float* d, const uint4& a, const uint2& b) {
    asm volatile(
        "mma.sync.aligned.m16n8k16.row.col.f32.f16.f16.f32 "
        "{%0,%1,%2,%3}, {%4,%5,%6,%7}, {%8,%9}, {%0,%1,%2,%3};"
        : "+f"(d[0]), "+f"(d[1]), "+f"(d[2]), "+f"(d[3])
        : "r"(a.x), "r"(a.y), "r"(a.z), "r"(a.w), "r"(b.x), "r"(b.y));
}

// ---------- small kernels ----------
__global__ void detect_lab_kernel(const int* __restrict__ lab) {
    if (threadIdx.x == 0) {
        int all_zero = 1;
        for (int i = 0; i < 256; ++i)
            if (lab[2 * i + 1] != 0) { all_zero = 0; break; }
        g_lab64 = all_zero;
    }
}

// One warp per row: fp16 features into m16n8k16 frag-ordered global copies,
// exact fp32 sq-norms + label into g_meta; also init ap/an.
__global__ void prep_kernel(const float* __restrict__ f,
                            const int* __restrict__ lab) {
    int warp = threadIdx.x >> 5, lane = threadIdx.x & 31;
    int row  = blockIdx.x * 8 + warp;
    const float* p = f + (size_t)row * DK;
    const int l64 = g_lab64;

    const int tile = row >> 7;         // 128-row tile
    const int n    = row & 127;        // row within tile

    char* abase = (char*)g_afrag + (size_t)tile * 32768;
    char* bbase = (char*)g_bfrag + (size_t)tile * 32768;

    // A: [ks][warp_m][mfrag][lane16B] ; warp grid 4x4
    const int warp_m = n >> 5, mfrag = (n >> 4) & 1, r16 = n & 15;
    // B: [ks][warp_n][nfrag][lane8B]
    const int warp_n = n >> 5, nfrag = (n >> 3) & 3, nn = n & 7;

    float s = 0.f;
    #pragma unroll
    for (int q = 0; q < 4; ++q) {
        int k = lane + q * 32;
        float v = p[k];
        s += v * v;
        __half hv = __float2half_rn(v);
        int ks = k >> 4, kk = k & 15;
        int lane_a = (r16 & 7) * 4 + ((kk & 7) >> 1);
        int reg_a  = ((kk >= 8) ? 2 : 0) + (r16 >> 3);
        *(__half*)(abase + ks * 4096 + warp_m * 1024 + mfrag * 512
                   + lane_a * 16 + reg_a * 4 + (kk & 1) * 2) = hv;
        int lane_b = nn * 4 + ((kk & 7) >> 1);
        int reg_b  = (kk >= 8) ? 1 : 0;
        *(__half*)(bbase + ks * 4096 + warp_n * 1024 + nfrag * 256
                   + lane_b * 8 + reg_b * 4 + (kk & 1) * 2) = hv;
    }
    #pragma unroll
    for (int m = 16; m; m >>= 1) s += __shfl_xor_sync(0xffffffffu, s, m);
    if (lane == 0) {
        g_meta[row] = make_float2(s, (float)lab[l64 ? (row << 1) : row]);
        g_ap[row] = 0u;
        g_an[row] = __float_as_uint(1e12f);
    }
}

__global__ void loss_kernel(float* __restrict__ out) {
    __shared__ float red[256];
    int t = threadIdx.x;
    int i = blockIdx.x * 256 + t;
    float ap = __uint_as_float(g_ap[i]);
    float an = __uint_as_float(g_an[i]);
    float dap = sqrtf(ap);
    float dan = (an > 9e11f) ? 1e6f : sqrtf(an);
    red[t] = fmaxf(0.f, 0.3f - (dan - dap));
    __syncthreads();
    #pragma unroll
    for (int s = 128; s; s >>= 1) {
        if (t < s) red[t] += red[t + s];
        __syncthreads();
    }
    if (t == 0) atomicAdd(out, red[0] * (1.0f / (float)NP));
}

// ---------- main fused fp16-MMA kernel ----------
// grid = 64 i-tiles x 2 j-halves, 512 threads (16 warps, 4x4 warp grid).
// Each warp: 32 i-rows (2 m-frags) x 32 j-cols (4 n-frags), K=128 in 8 k16 steps.
__global__ void __launch_bounds__(NTHR, 1)
triplet_mma(void) {
    extern __shared__ char smem[];
    char*   sA = smem;                        // 32768 B
    char*   sB = smem + 32768;                // 2 x 32768 B
    float2* sM = (float2*)(smem + 32768 * 3); // 2 x 128 float2
    const uint32_t sAu = smem_u32(sA);
    const uint32_t sBu = smem_u32(sB);
    const uint32_t sMu = smem_u32(sM);

    const int t = threadIdx.x, lane = t & 31, wid = t >> 5;
    const int warp_m = wid >> 2, warp_n = wid & 3;
    const int itile = blockIdx.x >> 1, jh = blockIdx.x & 1;
    const int i0  = itile * 128;
    const int jt0 = jh * NTJ;

    // prologue: A tile + B tile 0 + meta 0
    {
        const uint4* as = (const uint4*)((const char*)g_afrag + (size_t)itile * 32768);
        #pragma unroll
        for (int u = 0; u < 4; ++u)
            cp16(sAu + (t + u * 512) * 16, as + t + u * 512);
        const uint4* bs = (const uint4*)((const char*)g_bfrag + (size_t)jt0 * 32768);
        #pragma unroll
        for (int u = 0; u < 4; ++u)
            cp16(sBu + (t + u * 512) * 16, bs + t + u * 512);
        if (t < 128) cp8(sMu + t * 8, &g_meta[jt0 * 128 + t]);
        CP_COMMIT();
    }

    // row metadata (4 rows per thread: mf 2 x rr 2)
    float rsq[4], rlab[4];
    #pragma unroll
    for (int mf = 0; mf < 2; ++mf)
        #pragma unroll
        for (int rr = 0; rr < 2; ++rr) {
            float2 m = g_meta[i0 + warp_m * 32 + mf * 16 + rr * 8 + (lane >> 2)];
            rsq[mf * 2 + rr]  = m.x;
            rlab[mf * 2 + rr] = m.y;
        }

    float ap[4], an[4];
    #pragma unroll
    for (int r = 0; r < 4; ++r) { ap[r] = 0.f; an[r] = 1e12f; }

    for (int jt = 0; jt < NTJ; ++jt) {
        const int buf = jt & 1;
        // prefetch next tile into other buffer
        if (jt + 1 < NTJ) {
            const uint4* bs = (const uint4*)((const char*)g_bfrag
                                             + (size_t)(jt0 + jt + 1) * 32768);
            uint32_t bd = sBu + (uint32_t)(buf ^ 1) * 32768u;
            #pragma unroll
            for (int u = 0; u < 4; ++u)
                cp16(bd + (t + u * 512) * 16, bs + t + u * 512);
            if (t < 128)
                cp8(sMu + (buf ^ 1) * 1024 + t * 8,
                    &g_meta[(jt0 + jt + 1) * 128 + t]);
            CP_COMMIT();
            asm volatile("cp.async.wait_group 1;" ::: "memory");
        } else {
            asm volatile("cp.async.wait_group 0;" ::: "memory");
        }
        __syncthreads();

        // ---- MMA over K=128 (8 k16-steps), 2 m-frags x 4 n-frags ----
        float acc[2][4][4];
        #pragma unroll
        for (int mf = 0; mf < 2; ++mf)
            #pragma unroll
            for (int nf = 0; nf < 4; ++nf)
                #pragma unroll
                for (int e = 0; e < 4; ++e) acc[mf][nf][e] = 0.f;

        const uint4* Af = (const uint4*)sA + warp_m * 64;
        const uint2* Bf = (const uint2*)(sB + buf * 32768) + warp_n * 128;
        #pragma unroll
        for (int ks = 0; ks < 8; ++ks) {
            uint4 a[2]; uint2 b[4];
            #pragma unroll
            for (int mf = 0; mf < 2; ++mf) a[mf] = Af[ks * 256 + mf * 32 + lane];
            #pragma unroll
            for (int nf = 0; nf < 4; ++nf) b[nf] = Bf[ks * 512 + nf * 32 + lane];
            #pragma unroll
            for (int mf = 0; mf < 2; ++mf)
                #pragma unroll
                for (int nf = 0; nf < 4; ++nf)
                    mma_f16(acc[mf][nf], a[mf], b[nf]);
        }

        // ---- fused epilogue ----
        const float2* M = sM + buf * 128;
        const int jg0 = (jt0 + jt) * 128;
        const bool dia = (jg0 == i0);
        #pragma unroll
        for (int nf = 0; nf < 4; ++nf) {
            const int cl = warp_n * 32 + nf * 8 + (lane & 3) * 2;
            const float2 m0 = M[cl];
            const float2 m1 = M[cl + 1];
            #pragma unroll
            for (int mf = 0; mf < 2; ++mf)
                #pragma unroll
                for (int rr = 0; rr < 2; ++rr) {
                    const int r = mf * 2 + rr;
                    float d20 = fmaf(-2.f, acc[mf][nf][rr * 2 + 0], rsq[r] + m0.x);
                    float d21 = fmaf(-2.f, acc[mf][nf][rr * 2 + 1], rsq[r] + m1.x);
                    if (!dia) {
                        if (rlab[r] == m0.y) ap[r] = fmaxf(ap[r], d20);
                        else                 an[r] = fminf(an[r], d20);
                        if (rlab[r] == m1.y) ap[r] = fmaxf(ap[r], d21);
                        else                 an[r] = fminf(an[r], d21);
                    } else {
                        int gi = i0 + warp_m * 32 + mf * 16 + rr * 8 + (lane >> 2);
                        int gj = jg0 + cl;
                        if (rlab[r] == m0.y) {
                            if (gi != gj) ap[r] = fmaxf(ap[r], d20);
                        } else an[r] = fminf(an[r], d20);
                        if (rlab[r] == m1.y) {
                            if (gi != gj + 1) ap[r] = fmaxf(ap[r], d21);
                        } else an[r] = fminf(an[r], d21);
                    }
                }
        }
        __syncthreads();
    }

    // reduce over the 4 lanes sharing the same rows (lane%4 group)
    #pragma unroll
    for (int r = 0; r < 4; ++r) {
        ap[r] = fmaxf(ap[r], __shfl_xor_sync(0xffffffffu, ap[r], 1));
        ap[r] = fmaxf(ap[r], __shfl_xor_sync(0xffffffffu, ap[r], 2));
        an[r] = fminf(an[r], __shfl_xor_sync(0xffffffffu, an[r], 1));
        an[r] = fminf(an[r], __shfl_xor_sync(0xffffffffu, an[r], 2));
    }
    if ((lane & 3) == 0) {
        #pragma unroll
        for (int r = 0; r < 4; ++r) {
            int row = i0 + warp_m * 32 + (r >> 1) * 16 + (r & 1) * 8 + (lane >> 2);
            atomicMax(&g_ap[row], __float_as_uint(fmaxf(ap[r], 0.f)));
            atomicMin(&g_an[row], __float_as_uint(fmaxf(an[r], 0.f)));
        }
    }
}

// ---------- launch ----------
extern "C" void kernel_launch(void* const* d_in, const int* in_sizes, int n_in,
                              void* d_out, int out_size) {
    const float* feat = (const float*)d_in[0];
    const int*   lab  = (const int*)d_in[1];
    float*       out  = (float*)d_out;
    (void)in_sizes; (void)n_in; (void)out_size;

    const int smem_bytes = 32768 * 3 + 2048;   // 100352
    cudaFuncSetAttribute(triplet_mma,
                         cudaFuncAttributeMaxDynamicSharedMemorySize,
                         smem_bytes);

    cudaMemsetAsync(d_out, 0, sizeof(float));
    detect_lab_kernel<<<1, 32>>>(lab);
    prep_kernel<<<NP / 8, 256>>>(feat, lab);
    triplet_mma<<<(NP / 128) * 2, NTHR, smem_bytes>>>();
    loss_kernel<<<NP / 256, 256>>>(out);
}

// round 7
// speedup vs baseline: 13.4231x; 1.0194x over previous
#include <cuda_runtime.h>
#include <cuda_fp16.h>
#include <cstdint>

#define NP 8192
#define DK 128
#define NTJ 32      // j-tiles per CTA (half of 64)
#define NTHR 512

__device__ __half   g_afrag[NP * DK];   // A-fragment-ordered fp16 features
__device__ __half   g_bfrag[NP * DK];   // B-fragment-ordered fp16 features
__device__ float2   g_meta[NP];         // (sq_norm, label as float)
__device__ unsigned g_ap[NP];
__device__ unsigned g_an[NP];
__device__ int      g_lab64;

// ---------- helpers ----------
__device__ __forceinline__ uint32_t smem_u32(const void* p) {
    uint32_t a;
    asm("{ .reg .u64 t; cvta.to.shared.u64 t, %1; cvt.u32.u64 %0, t; }"
        : "=r"(a) : "l"(p));
    return a;
}
__device__ __forceinline__ void cp16(uint32_t dst, const void* src) {
    asm volatile("cp.async.cg.shared.global [%0], [%1], 16;" :: "r"(dst), "l"(src));
}
__device__ __forceinline__ void cp8(uint32_t dst, const void* src) {
    asm volatile("cp.async.ca.shared.global [%0], [%1], 8;" :: "r"(dst), "l"(src));
}
#define CP_COMMIT() asm volatile("cp.async.commit_group;" ::: "memory")

__device__ __forceinline__ void mma_f16(float* d, const uint4& a, const uint2& b) {
    asm volatile(
        "mma.sync.aligned.m16n8k16.row.col.f32.f16.f16.f32 "
        "{%0,%1,%2,%3}, {%4,%5,%6,%7}, {%8,%9}, {%0,%1,%2,%3};"
        : "+f"(d[0]), "+f"(d[1]), "+f"(d[2]), "+f"(d[3])
        : "r"(a.x), "r"(a.y), "r"(a.z), "r"(a.w), "r"(b.x), "r"(b.y));
}

// ---------- small kernels ----------
__global__ void detect_lab_kernel(const int* __restrict__ lab) {
    int t = threadIdx.x;
    unsigned nz = __ballot_sync(0xffffffffu,
        (lab[2 * (t * 8 + 0) + 1] | lab[2 * (t * 8 + 1) + 1] |
         lab[2 * (t * 8 + 2) + 1] | lab[2 * (t * 8 + 3) + 1] |
         lab[2 * (t * 8 + 4) + 1] | lab[2 * (t * 8 + 5) + 1] |
         lab[2 * (t * 8 + 6) + 1] | lab[2 * (t * 8 + 7) + 1]) != 0);
    if (t == 0) g_lab64 = (nz == 0u);
}

// One warp per row: fp16 features into m16n8k16 frag-ordered global copies,
// exact fp32 sq-norms + label into g_meta; also init ap/an.
__global__ void prep_kernel(const float* __restrict__ f,
                            const int* __restrict__ lab) {
    int warp = threadIdx.x >> 5, lane = threadIdx.x & 31;
    int row  = blockIdx.x * 8 + warp;
    const float* p = f + (size_t)row * DK;
    const int l64 = g_lab64;

    const int tile = row >> 7;         // 128-row tile
    const int n    = row & 127;        // row within tile

    char* abase = (char*)g_afrag + (size_t)tile * 32768;
    char* bbase = (char*)g_bfrag + (size_t)tile * 32768;

    // A: [ks][warp_m][mfrag][lane16B] ; warp grid 4x4
    const int warp_m = n >> 5, mfrag = (n >> 4) & 1, r16 = n & 15;
    // B: [ks][warp_n][nfrag][lane8B]
    const int warp_n = n >> 5, nfrag = (n >> 3) & 3, nn = n & 7;

    float s = 0.f;
    #pragma unroll
    for (int q = 0; q < 4; ++q) {
        int k = lane + q * 32;
        float v = p[k];
        s += v * v;
        __half hv = __float2half_rn(v);
        int ks = k >> 4, kk = k & 15;
        int lane_a = (r16 & 7) * 4 + ((kk & 7) >> 1);
        int reg_a  = ((kk >= 8) ? 2 : 0) + (r16 >> 3);
        *(__half*)(abase + ks * 4096 + warp_m * 1024 + mfrag * 512
                   + lane_a * 16 + reg_a * 4 + (kk & 1) * 2) = hv;
        int lane_b = nn * 4 + ((kk & 7) >> 1);
        int reg_b  = (kk >= 8) ? 1 : 0;
        *(__half*)(bbase + ks * 4096 + warp_n * 1024 + nfrag * 256
                   + lane_b * 8 + reg_b * 4 + (kk & 1) * 2) = hv;
    }
    #pragma unroll
    for (int m = 16; m; m >>= 1) s += __shfl_xor_sync(0xffffffffu, s, m);
    if (lane == 0) {
        g_meta[row] = make_float2(s, (float)lab[l64 ? (row << 1) : row]);
        g_ap[row] = 0u;
        g_an[row] = __float_as_uint(1e12f);
    }
}

__global__ void loss_kernel(float* __restrict__ out) {
    __shared__ float red[256];
    int t = threadIdx.x;
    int i = blockIdx.x * 256 + t;
    float ap = __uint_as_float(g_ap[i]);
    float an = __uint_as_float(g_an[i]);
    float dap = sqrtf(ap);
    float dan = (an > 9e11f) ? 1e6f : sqrtf(an);
    red[t] = fmaxf(0.f, 0.3f - (dan - dap));
    __syncthreads();
    #pragma unroll
    for (int s = 128; s; s >>= 1) {
        if (t < s) red[t] += red[t + s];
        __syncthreads();
    }
    if (t == 0) atomicAdd(out, red[0] * (1.0f / (float)NP));
}

// ---------- main fused fp16-MMA kernel, pipelined epilogue ----------
// grid = 64 i-tiles x 2 j-halves, 512 threads (16 warps, 4x4 warp grid).
// Two register acc sets: tile jt's MMAs issue before tile jt-1's epilogue,
// so the epilogue (fma/alu) overlaps in-flight HMMAs (tensor pipe).
__global__ void __launch_bounds__(NTHR, 1)
triplet_mma(void) {
    extern __shared__ char smem[];
    char*   sA = smem;                        // 32768 B
    char*   sB = smem + 32768;                // 2 x 32768 B
    float2* sM = (float2*)(smem + 32768 * 3); // 4 x 128 float2 (ring)
    const uint32_t sAu = smem_u32(sA);
    const uint32_t sBu = smem_u32(sB);
    const uint32_t sMu = smem_u32(sM);

    const int t = threadIdx.x, lane = t & 31, wid = t >> 5;
    const int warp_m = wid >> 2, warp_n = wid & 3;
    const int itile = blockIdx.x >> 1, jh = blockIdx.x & 1;
    const int i0  = itile * 128;
    const int jt0 = jh * NTJ;

    // prologue: A tile + B tile 0 + meta slot 0
    {
        const uint4* as = (const uint4*)((const char*)g_afrag + (size_t)itile * 32768);
        #pragma unroll
        for (int u = 0; u < 4; ++u)
            cp16(sAu + (t + u * 512) * 16, as + t + u * 512);
        const uint4* bs = (const uint4*)((const char*)g_bfrag + (size_t)jt0 * 32768);
        #pragma unroll
        for (int u = 0; u < 4; ++u)
            cp16(sBu + (t + u * 512) * 16, bs + t + u * 512);
        if (t < 128) cp8(sMu + t * 8, &g_meta[jt0 * 128 + t]);
        CP_COMMIT();
    }

    // row metadata (4 rows per thread: mf 2 x rr 2)
    float rsq[4], rlab[4];
    #pragma unroll
    for (int mf = 0; mf < 2; ++mf)
        #pragma unroll
        for (int rr = 0; rr < 2; ++rr) {
            float2 m = g_meta[i0 + warp_m * 32 + mf * 16 + rr * 8 + (lane >> 2)];
            rsq[mf * 2 + rr]  = m.x;
            rlab[mf * 2 + rr] = m.y;
        }

    float ap[4], an[4];
    #pragma unroll
    for (int r = 0; r < 4; ++r) { ap[r] = 0.f; an[r] = 1e12f; }

    float accE[2][4][4], accO[2][4][4];   // even / odd tile accumulators

    // ---- MMA for one tile into acc ----
    #define MMA_TILE(JT, ACC) do {                                          \
        _Pragma("unroll")                                                   \
        for (int mf = 0; mf < 2; ++mf)                                      \
            _Pragma("unroll")                                               \
            for (int nf = 0; nf < 4; ++nf)                                  \
                _Pragma("unroll")                                           \
                for (int e = 0; e < 4; ++e) ACC[mf][nf][e] = 0.f;           \
        const uint4* Af = (const uint4*)sA + warp_m * 64;                   \
        const uint2* Bf = (const uint2*)(sB + ((JT) & 1) * 32768)           \
                          + warp_n * 128;                                   \
        _Pragma("unroll")                                                   \
        for (int ks = 0; ks < 8; ++ks) {                                    \
            uint4 a[2]; uint2 b[4];                                         \
            _Pragma("unroll")                                               \
            for (int mf = 0; mf < 2; ++mf)                                  \
                a[mf] = Af[ks * 256 + mf * 32 + lane];                      \
            _Pragma("unroll")                                               \
            for (int nf = 0; nf < 4; ++nf)                                  \
                b[nf] = Bf[ks * 512 + nf * 32 + lane];                      \
            _Pragma("unroll")                                               \
            for (int mf = 0; mf < 2; ++mf)                                  \
                _Pragma("unroll")                                           \
                for (int nf = 0; nf < 4; ++nf)                              \
                    mma_f16(ACC[mf][nf], a[mf], b[nf]);                     \
        }                                                                   \
    } while (0)

    // ---- fused epilogue for tile ET from acc ----
    #define EPI_TILE(ET, ACC) do {                                          \
        const float2* M = sM + ((ET) & 3) * 128;                            \
        const int jg0 = (jt0 + (ET)) * 128;                                 \
        const bool dia = (jg0 == i0);                                       \
        _Pragma("unroll")                                                   \
        for (int nf = 0; nf < 4; ++nf) {                                    \
            const int cl = warp_n * 32 + nf * 8 + (lane & 3) * 2;           \
            const float2 m0 = M[cl];                                        \
            const float2 m1 = M[cl + 1];                                    \
            _Pragma("unroll")                                               \
            for (int mf = 0; mf < 2; ++mf)                                  \
                _Pragma("unroll")                                           \
                for (int rr = 0; rr < 2; ++rr) {                            \
                    const int r = mf * 2 + rr;                              \
                    float d20 = fmaf(-2.f, ACC[mf][nf][rr * 2 + 0],         \
                                     rsq[r] + m0.x);                        \
                    float d21 = fmaf(-2.f, ACC[mf][nf][rr * 2 + 1],         \
                                     rsq[r] + m1.x);                        \
                    if (!dia) {                                             \
                        if (rlab[r] == m0.y) ap[r] = fmaxf(ap[r], d20);     \
                        else                 an[r] = fminf(an[r], d20);     \
                        if (rlab[r] == m1.y) ap[r] = fmaxf(ap[r], d21);     \
                        else                 an[r] = fminf(an[r], d21);     \
                    } else {                                                \
                        int gi = i0 + warp_m * 32 + mf * 16 + rr * 8        \
                                 + (lane >> 2);                             \
                        int gj = jg0 + cl;                                  \
                        if (rlab[r] == m0.y) {                              \
                            if (gi != gj) ap[r] = fmaxf(ap[r], d20);        \
                        } else an[r] = fminf(an[r], d20);                   \
                        if (rlab[r] == m1.y) {                              \
                            if (gi != gj + 1) ap[r] = fmaxf(ap[r], d21);    \
                        } else an[r] = fminf(an[r], d21);                   \
                    }                                                       \
                }                                                           \
        }                                                                   \
    } while (0)

    // ---- one pipeline step: prefetch JT+1, MMA JT, epilogue JT-1 ----
    #define STEP(JT, ACCC, ACCP) do {                                       \
        if ((JT) + 1 < NTJ) {                                               \
            const uint4* bs = (const uint4*)((const char*)g_bfrag           \
                              + (size_t)(jt0 + (JT) + 1) * 32768);          \
            uint32_t bd = sBu + (uint32_t)(((JT) + 1) & 1) * 32768u;        \
            _Pragma("unroll")                                               \
            for (int u = 0; u < 4; ++u)                                     \
                cp16(bd + (t + u * 512) * 16, bs + t + u * 512);            \
            if (t < 128)                                                    \
                cp8(sMu + (((JT) + 1) & 3) * 1024 + t * 8,                  \
                    &g_meta[(jt0 + (JT) + 1) * 128 + t]);                   \
            CP_COMMIT();                                                    \
            asm volatile("cp.async.wait_group 1;" ::: "memory");            \
        } else {                                                            \
            asm volatile("cp.async.wait_group 0;" ::: "memory");            \
        }                                                                   \
        __syncthreads();                                                    \
        MMA_TILE(JT, ACCC);                                                 \
        if ((JT) > 0) EPI_TILE((JT) - 1, ACCP);                             \
        __syncthreads();                                                    \
    } while (0)

    for (int jt = 0; jt < NTJ; jt += 2) {
        STEP(jt,     accE, accO);
        STEP(jt + 1, accO, accE);
    }
    EPI_TILE(NTJ - 1, accO);

    // reduce over the 4 lanes sharing the same rows (lane%4 group)
    #pragma unroll
    for (int r = 0; r < 4; ++r) {
        ap[r] = fmaxf(ap[r], __shfl_xor_sync(0xffffffffu, ap[r], 1));
        ap[r] = fmaxf(ap[r], __shfl_xor_sync(0xffffffffu, ap[r], 2));
        an[r] = fminf(an[r], __shfl_xor_sync(0xffffffffu, an[r], 1));
        an[r] = fminf(an[r], __shfl_xor_sync(0xffffffffu, an[r], 2));
    }
    if ((lane & 3) == 0) {
        #pragma unroll
        for (int r = 0; r < 4; ++r) {
            int row = i0 + warp_m * 32 + (r >> 1) * 16 + (r & 1) * 8 + (lane >> 2);
            atomicMax(&g_ap[row], __float_as_uint(fmaxf(ap[r], 0.f)));
            atomicMin(&g_an[row], __float_as_uint(fmaxf(an[r], 0.f)));
        }
    }
    #undef MMA_TILE
    #undef EPI_TILE
    #undef STEP
}

// ---------- launch ----------
extern "C" void kernel_launch(void* const* d_in, const int* in_sizes, int n_in,
                              void* d_out, int out_size) {
    const float* feat = (const float*)d_in[0];
    const int*   lab  = (const int*)d_in[1];
    float*       out  = (float*)d_out;
    (void)in_sizes; (void)n_in; (void)out_size;

    const int smem_bytes = 32768 * 3 + 4096;   // 102400
    cudaFuncSetAttribute(triplet_mma,
                         cudaFuncAttributeMaxDynamicSharedMemorySize,
                         smem_bytes);

    cudaMemsetAsync(d_out, 0, sizeof(float));
    detect_lab_kernel<<<1, 32>>>(lab);
    prep_kernel<<<NP / 8, 256>>>(feat, lab);
    triplet_mma<<<(NP / 128) * 2, NTHR, smem_bytes>>>();
    loss_kernel<<<NP / 256, 256>>>(out);
}

// round 8
// speedup vs baseline: 16.1174x; 1.2007x over previous
#include <cuda_runtime.h>
#include <cuda_fp16.h>
#include <cstdint>

#define NP 8192
#define DK 128
#define NTJ 16      // j-tiles per CTA (quarter of 64)
#define NTHR 256

__device__ __half   g_afrag[NP * DK];   // A-fragment-ordered fp16 features
__device__ __half   g_bfrag[NP * DK];   // B-fragment-ordered fp16 features
__device__ float2   g_meta[NP];         // (sq_norm, label as float)
__device__ unsigned g_ap[NP];
__device__ unsigned g_an[NP];
__device__ int      g_lab64;

// ---------- helpers ----------
__device__ __forceinline__ uint32_t smem_u32(const void* p) {
    uint32_t a;
    asm("{ .reg .u64 t; cvta.to.shared.u64 t, %1; cvt.u32.u64 %0, t; }"
        : "=r"(a) : "l"(p));
    return a;
}
__device__ __forceinline__ void cp16(uint32_t dst, const void* src) {
    asm volatile("cp.async.cg.shared.global [%0], [%1], 16;" :: "r"(dst), "l"(src));
}
__device__ __forceinline__ void cp8(uint32_t dst, const void* src) {
    asm volatile("cp.async.ca.shared.global [%0], [%1], 8;" :: "r"(dst), "l"(src));
}
#define CP_COMMIT() asm volatile("cp.async.commit_group;" ::: "memory")

__device__ __forceinline__ void mma_f16(float* d, const uint4& a, const uint2& b) {
    asm volatile(
        "mma.sync.aligned.m16n8k16.row.col.f32.f16.f16.f32 "
        "{%0,%1,%2,%3}, {%4,%5,%6,%7}, {%8,%9}, {%0,%1,%2,%3};"
        : "+f"(d[0]), "+f"(d[1]), "+f"(d[2]), "+f"(d[3])
        : "r"(a.x), "r"(a.y), "r"(a.z), "r"(a.w), "r"(b.x), "r"(b.y));
}

// ---------- small kernels ----------
__global__ void detect_lab_kernel(const int* __restrict__ lab) {
    int t = threadIdx.x;
    unsigned nz = __ballot_sync(0xffffffffu,
        (lab[2 * (t * 8 + 0) + 1] | lab[2 * (t * 8 + 1) + 1] |
         lab[2 * (t * 8 + 2) + 1] | lab[2 * (t * 8 + 3) + 1] |
         lab[2 * (t * 8 + 4) + 1] | lab[2 * (t * 8 + 5) + 1] |
         lab[2 * (t * 8 + 6) + 1] | lab[2 * (t * 8 + 7) + 1]) != 0);
    if (t == 0) g_lab64 = (nz == 0u);
}

// One warp per row: fp16 features into frag-ordered global copies
// (warp grid 2x4: A mf=4, B nf=4), exact fp32 sq-norms + label; init ap/an.
__global__ void prep_kernel(const float* __restrict__ f,
                            const int* __restrict__ lab) {
    int warp = threadIdx.x >> 5, lane = threadIdx.x & 31;
    int row  = blockIdx.x * 8 + warp;
    const float* p = f + (size_t)row * DK;
    const int l64 = g_lab64;

    const int tile = row >> 7;         // 128-row tile
    const int n    = row & 127;        // row within tile

    char* abase = (char*)g_afrag + (size_t)tile * 32768;
    char* bbase = (char*)g_bfrag + (size_t)tile * 32768;

    // A: [ks][warp_m(2)][mfrag(4)][lane16B]
    const int warp_m = n >> 6, mfrag = (n >> 4) & 3, r16 = n & 15;
    // B: [ks][warp_n(4)][nfrag(4)][lane8B]
    const int warp_n = n >> 5, nfrag = (n >> 3) & 3, nn = n & 7;

    float s = 0.f;
    #pragma unroll
    for (int q = 0; q < 4; ++q) {
        int k = lane + q * 32;
        float v = p[k];
        s += v * v;
        __half hv = __float2half_rn(v);
        int ks = k >> 4, kk = k & 15;
        int lane_a = (r16 & 7) * 4 + ((kk & 7) >> 1);
        int reg_a  = ((kk >= 8) ? 2 : 0) + (r16 >> 3);
        *(__half*)(abase + ks * 4096 + warp_m * 2048 + mfrag * 512
                   + lane_a * 16 + reg_a * 4 + (kk & 1) * 2) = hv;
        int lane_b = nn * 4 + ((kk & 7) >> 1);
        int reg_b  = (kk >= 8) ? 1 : 0;
        *(__half*)(bbase + ks * 4096 + warp_n * 1024 + nfrag * 256
                   + lane_b * 8 + reg_b * 4 + (kk & 1) * 2) = hv;
    }
    #pragma unroll
    for (int m = 16; m; m >>= 1) s += __shfl_xor_sync(0xffffffffu, s, m);
    if (lane == 0) {
        g_meta[row] = make_float2(s, (float)lab[l64 ? (row << 1) : row]);
        g_ap[row] = 0u;
        g_an[row] = __float_as_uint(1e12f);
    }
}

__global__ void loss_kernel(float* __restrict__ out) {
    __shared__ float red[256];
    int t = threadIdx.x;
    int i = blockIdx.x * 256 + t;
    float ap = __uint_as_float(g_ap[i]);
    float an = __uint_as_float(g_an[i]);
    float dap = sqrtf(ap);
    float dan = (an > 9e11f) ? 1e6f : sqrtf(an);
    red[t] = fmaxf(0.f, 0.3f - (dan - dap));
    __syncthreads();
    #pragma unroll
    for (int s = 128; s; s >>= 1) {
        if (t < s) red[t] += red[t + s];
        __syncthreads();
    }
    if (t == 0) atomicAdd(out, red[0] * (1.0f / (float)NP));
}

// ---------- main fused fp16-MMA kernel ----------
// grid = 64 i-tiles x 4 j-quarters = 256 CTAs (one wave at 2 CTA/SM).
// 256 threads (8 warps, 2x4 warp grid). Each warp: 64 i-rows (4 m-frags)
// x 32 j-cols (4 n-frags). Smem reads/tile: 192KB (vs 256KB at 4x4).
__global__ void __launch_bounds__(NTHR, 2)
triplet_mma(void) {
    extern __shared__ char smem[];
    char*   sA = smem;                        // 32768 B
    char*   sB = smem + 32768;                // 2 x 32768 B
    float2* sM = (float2*)(smem + 32768 * 3); // 2 x 128 float2
    const uint32_t sAu = smem_u32(sA);
    const uint32_t sBu = smem_u32(sB);
    const uint32_t sMu = smem_u32(sM);

    const int t = threadIdx.x, lane = t & 31, wid = t >> 5;
    const int warp_m = wid >> 2, warp_n = wid & 3;
    const int itile = blockIdx.x >> 2, jq = blockIdx.x & 3;
    const int i0  = itile * 128;
    const int jt0 = jq * NTJ;

    // prologue: A tile + B tile 0 + meta 0
    {
        const uint4* as = (const uint4*)((const char*)g_afrag + (size_t)itile * 32768);
        #pragma unroll
        for (int u = 0; u < 8; ++u)
            cp16(sAu + (t + u * 256) * 16, as + t + u * 256);
        const uint4* bs = (const uint4*)((const char*)g_bfrag + (size_t)jt0 * 32768);
        #pragma unroll
        for (int u = 0; u < 8; ++u)
            cp16(sBu + (t + u * 256) * 16, bs + t + u * 256);
        if (t < 128) cp8(sMu + t * 8, &g_meta[jt0 * 128 + t]);
        CP_COMMIT();
    }

    // row metadata (8 rows per thread: mf 4 x rr 2)
    float rsq[8], rlab[8];
    #pragma unroll
    for (int mf = 0; mf < 4; ++mf)
        #pragma unroll
        for (int rr = 0; rr < 2; ++rr) {
            float2 m = g_meta[i0 + warp_m * 64 + mf * 16 + rr * 8 + (lane >> 2)];
            rsq[mf * 2 + rr]  = m.x;
            rlab[mf * 2 + rr] = m.y;
        }

    float ap[8], an[8];
    #pragma unroll
    for (int r = 0; r < 8; ++r) { ap[r] = 0.f; an[r] = 1e12f; }

    for (int jt = 0; jt < NTJ; ++jt) {
        const int buf = jt & 1;
        // prefetch next B tile + meta
        if (jt + 1 < NTJ) {
            const uint4* bs = (const uint4*)((const char*)g_bfrag
                                             + (size_t)(jt0 + jt + 1) * 32768);
            uint32_t bd = sBu + (uint32_t)(buf ^ 1) * 32768u;
            #pragma unroll
            for (int u = 0; u < 8; ++u)
                cp16(bd + (t + u * 256) * 16, bs + t + u * 256);
            if (t < 128)
                cp8(sMu + (buf ^ 1) * 1024 + t * 8,
                    &g_meta[(jt0 + jt + 1) * 128 + t]);
            CP_COMMIT();
            asm volatile("cp.async.wait_group 1;" ::: "memory");
        } else {
            asm volatile("cp.async.wait_group 0;" ::: "memory");
        }
        __syncthreads();

        // ---- MMA over K=128 (8 k16-steps), 4 m-frags x 4 n-frags ----
        float acc[4][4][4];
        #pragma unroll
        for (int mf = 0; mf < 4; ++mf)
            #pragma unroll
            for (int nf = 0; nf < 4; ++nf)
                #pragma unroll
                for (int e = 0; e < 4; ++e) acc[mf][nf][e] = 0.f;

        const uint4* Af = (const uint4*)sA + warp_m * 128;
        const uint2* Bf = (const uint2*)(sB + buf * 32768) + warp_n * 128;
        #pragma unroll
        for (int ks = 0; ks < 8; ++ks) {
            uint4 a[4]; uint2 b[4];
            #pragma unroll
            for (int mf = 0; mf < 4; ++mf) a[mf] = Af[ks * 256 + mf * 32 + lane];
            #pragma unroll
            for (int nf = 0; nf < 4; ++nf) b[nf] = Bf[ks * 512 + nf * 32 + lane];
            #pragma unroll
            for (int mf = 0; mf < 4; ++mf)
                #pragma unroll
                for (int nf = 0; nf < 4; ++nf)
                    mma_f16(acc[mf][nf], a[mf], b[nf]);
        }

        // ---- fused epilogue ----
        const float2* M = sM + buf * 128;
        const int jg0 = (jt0 + jt) * 128;
        const bool dia = (jg0 == i0);
        #pragma unroll
        for (int nf = 0; nf < 4; ++nf) {
            const int cl = warp_n * 32 + nf * 8 + (lane & 3) * 2;
            const float2 m0 = M[cl];
            const float2 m1 = M[cl + 1];
            #pragma unroll
            for (int mf = 0; mf < 4; ++mf)
                #pragma unroll
                for (int rr = 0; rr < 2; ++rr) {
                    const int r = mf * 2 + rr;
                    float d20 = fmaf(-2.f, acc[mf][nf][rr * 2 + 0], rsq[r] + m0.x);
                    float d21 = fmaf(-2.f, acc[mf][nf][rr * 2 + 1], rsq[r] + m1.x);
                    if (!dia) {
                        if (rlab[r] == m0.y) ap[r] = fmaxf(ap[r], d20);
                        else                 an[r] = fminf(an[r], d20);
                        if (rlab[r] == m1.y) ap[r] = fmaxf(ap[r], d21);
                        else                 an[r] = fminf(an[r], d21);
                    } else {
                        int gi = i0 + warp_m * 64 + mf * 16 + rr * 8 + (lane >> 2);
                        int gj = jg0 + cl;
                        if (rlab[r] == m0.y) {
                            if (gi != gj) ap[r] = fmaxf(ap[r], d20);
                        } else an[r] = fminf(an[r], d20);
                        if (rlab[r] == m1.y) {
                            if (gi != gj + 1) ap[r] = fmaxf(ap[r], d21);
                        } else an[r] = fminf(an[r], d21);
                    }
                }
        }
        __syncthreads();
    }

    // reduce over the 4 lanes sharing the same rows (lane%4 group)
    #pragma unroll
    for (int r = 0; r < 8; ++r) {
        ap[r] = fmaxf(ap[r], __shfl_xor_sync(0xffffffffu, ap[r], 1));
        ap[r] = fmaxf(ap[r], __shfl_xor_sync(0xffffffffu, ap[r], 2));
        an[r] = fminf(an[r], __shfl_xor_sync(0xffffffffu, an[r], 1));
        an[r] = fminf(an[r], __shfl_xor_sync(0xffffffffu, an[r], 2));
    }
    if ((lane & 3) == 0) {
        #pragma unroll
        for (int r = 0; r < 8; ++r) {
            int row = i0 + warp_m * 64 + (r >> 1) * 16 + (r & 1) * 8 + (lane >> 2);
            atomicMax(&g_ap[row], __float_as_uint(fmaxf(ap[r], 0.f)));
            atomicMin(&g_an[row], __float_as_uint(fmaxf(an[r], 0.f)));
        }
    }
}

// ---------- launch ----------
extern "C" void kernel_launch(void* const* d_in, const int* in_sizes, int n_in,
                              void* d_out, int out_size) {
    const float* feat = (const float*)d_in[0];
    const int*   lab  = (const int*)d_in[1];
    float*       out  = (float*)d_out;
    (void)in_sizes; (void)n_in; (void)out_size;

    const int smem_bytes = 32768 * 3 + 2048;   // 100352
    cudaFuncSetAttribute(triplet_mma,
                         cudaFuncAttributeMaxDynamicSharedMemorySize,
                         smem_bytes);

    cudaMemsetAsync(d_out, 0, sizeof(float));
    detect_lab_kernel<<<1, 32>>>(lab);
    prep_kernel<<<NP / 8, 256>>>(feat, lab);
    triplet_mma<<<(NP / 128) * 4, NTHR, smem_bytes>>>();
    loss_kernel<<<NP / 256, 256>>>(out);
}

// round 9
// speedup vs baseline: 19.1453x; 1.1879x over previous
#include <cuda_runtime.h>
#include <cuda_fp16.h>
#include <cstdint>

#define NP 8192
#define DK 128
#define NTHR 256

__device__ __half   g_afrag[NP * DK];   // A-fragment-ordered fp16 features
__device__ __half   g_bfrag[NP * DK];   // B-fragment-ordered fp16 features
__device__ float2   g_meta[NP];         // (sq_norm, label as float)
__device__ unsigned g_ap[NP];
__device__ unsigned g_an[NP];
__device__ int      g_done = 0;

// ---------- helpers ----------
__device__ __forceinline__ uint32_t smem_u32(const void* p) {
    uint32_t a;
    asm("{ .reg .u64 t; cvta.to.shared.u64 t, %1; cvt.u32.u64 %0, t; }"
        : "=r"(a) : "l"(p));
    return a;
}
__device__ __forceinline__ void cp16(uint32_t dst, const void* src) {
    asm volatile("cp.async.cg.shared.global [%0], [%1], 16;" :: "r"(dst), "l"(src));
}
__device__ __forceinline__ void cp8(uint32_t dst, const void* src) {
    asm volatile("cp.async.ca.shared.global [%0], [%1], 8;" :: "r"(dst), "l"(src));
}
#define CP_COMMIT() asm volatile("cp.async.commit_group;" ::: "memory")

__device__ __forceinline__ void mma_f16(float* d, const uint4& a, const uint2& b) {
    asm volatile(
        "mma.sync.aligned.m16n8k16.row.col.f32.f16.f16.f32 "
        "{%0,%1,%2,%3}, {%4,%5,%6,%7}, {%8,%9}, {%0,%1,%2,%3};"
        : "+f"(d[0]), "+f"(d[1]), "+f"(d[2]), "+f"(d[3])
        : "r"(a.x), "r"(a.y), "r"(a.z), "r"(a.w), "r"(b.x), "r"(b.y));
}

// ---------- prep: fp16 frag copies + meta + init (detection inlined) ----------
__global__ void prep_kernel(const float* __restrict__ f,
                            const int* __restrict__ lab) {
    const int t = threadIdx.x;
    // label layout detection (identical result in every block)
    int nz = (lab[2 * t + 1] != 0);
    int l64 = !__syncthreads_or(nz);

    int warp = t >> 5, lane = t & 31;
    int row  = blockIdx.x * 8 + warp;
    const float* p = f + (size_t)row * DK;

    const int tile = row >> 7;         // 128-row tile
    const int n    = row & 127;        // row within tile

    char* abase = (char*)g_afrag + (size_t)tile * 32768;
    char* bbase = (char*)g_bfrag + (size_t)tile * 32768;

    // A: [ks][warp_m(2)][mfrag(4)][lane16B]
    const int warp_m = n >> 6, mfrag = (n >> 4) & 3, r16 = n & 15;
    // B: [ks][warp_n(4)][nfrag(4)][lane8B]
    const int warp_n = n >> 5, nfrag = (n >> 3) & 3, nn = n & 7;

    float s = 0.f;
    #pragma unroll
    for (int q = 0; q < 4; ++q) {
        int k = lane + q * 32;
        float v = p[k];
        s += v * v;
        __half hv = __float2half_rn(v);
        int ks = k >> 4, kk = k & 15;
        int lane_a = (r16 & 7) * 4 + ((kk & 7) >> 1);
        int reg_a  = ((kk >= 8) ? 2 : 0) + (r16 >> 3);
        *(__half*)(abase + ks * 4096 + warp_m * 2048 + mfrag * 512
                   + lane_a * 16 + reg_a * 4 + (kk & 1) * 2) = hv;
        int lane_b = nn * 4 + ((kk & 7) >> 1);
        int reg_b  = (kk >= 8) ? 1 : 0;
        *(__half*)(bbase + ks * 4096 + warp_n * 1024 + nfrag * 256
                   + lane_b * 8 + reg_b * 4 + (kk & 1) * 2) = hv;
    }
    #pragma unroll
    for (int m = 16; m; m >>= 1) s += __shfl_xor_sync(0xffffffffu, s, m);
    if (lane == 0) {
        g_meta[row] = make_float2(s, (float)lab[l64 ? (row << 1) : row]);
        g_ap[row] = 0u;
        g_an[row] = __float_as_uint(1e12f);
    }
}

// ---------- main fused fp16-MMA kernel (symmetric tiles) ----------
// grid = 64 it x 4 d-groups = 256 CTAs. Tile (it, jt=(it+d)&63), d in the
// group's range (g3 adds d=32 only for it<32) -> upper triangle exactly once.
// Off-diagonal tiles update BOTH row stats (it rows) and col stats (jt rows).
// Last CTA computes the final loss (fused, no extra launch).
__global__ void __launch_bounds__(NTHR, 2)
triplet_mma(float* __restrict__ out) {
    extern __shared__ char smem[];
    char*   sA  = smem;                        // 32768
    char*   sB  = smem + 32768;                // 2 x 32768
    float2* sMA = (float2*)(smem + 98304);     // 128 float2
    float2* sMB = (float2*)(smem + 99328);     // 2 x 128 float2
    const uint32_t sAu  = smem_u32(sA);
    const uint32_t sBu  = smem_u32(sB);
    const uint32_t sMAu = smem_u32(sMA);
    const uint32_t sMBu = smem_u32(sMB);

    const int t = threadIdx.x, lane = t & 31, wid = t >> 5;
    const int warp_m = wid >> 2, warp_n = wid & 3;
    const int it = blockIdx.x >> 2, g = blockIdx.x & 3;
    const int i0 = it * 128;
    const int d0 = g * 8;
    const int nd = 8 + ((g == 3 && it < 32) ? 1 : 0);

    // prologue: A tile + metaA + B tile (d0) + metaB
    {
        const uint4* as = (const uint4*)((const char*)g_afrag + (size_t)it * 32768);
        #pragma unroll
        for (int u = 0; u < 8; ++u)
            cp16(sAu + (t + u * 256) * 16, as + t + u * 256);
        int jt = (it + d0) & 63;
        const uint4* bs = (const uint4*)((const char*)g_bfrag + (size_t)jt * 32768);
        #pragma unroll
        for (int u = 0; u < 8; ++u)
            cp16(sBu + (t + u * 256) * 16, bs + t + u * 256);
        if (t < 128) {
            cp8(sMAu + t * 8, &g_meta[i0 + t]);
            cp8(sMBu + t * 8, &g_meta[jt * 128 + t]);
        }
        CP_COMMIT();
    }

    float ap[8], an[8];
    #pragma unroll
    for (int r = 0; r < 8; ++r) { ap[r] = 0.f; an[r] = 1e12f; }

    for (int s = 0; s < nd; ++s) {
        const int d   = d0 + s;
        const int jt  = (it + d) & 63;
        const int buf = s & 1;
        // prefetch next B tile + meta
        if (s + 1 < nd) {
            int jn = (it + d + 1) & 63;
            const uint4* bs = (const uint4*)((const char*)g_bfrag + (size_t)jn * 32768);
            uint32_t bd = sBu + (uint32_t)(buf ^ 1) * 32768u;
            #pragma unroll
            for (int u = 0; u < 8; ++u)
                cp16(bd + (t + u * 256) * 16, bs + t + u * 256);
            if (t < 128)
                cp8(sMBu + (buf ^ 1) * 1024 + t * 8, &g_meta[jn * 128 + t]);
            CP_COMMIT();
            asm volatile("cp.async.wait_group 1;" ::: "memory");
        } else {
            asm volatile("cp.async.wait_group 0;" ::: "memory");
        }
        __syncthreads();

        // ---- MMA over K=128 (8 k16-steps), 4 m-frags x 4 n-frags ----
        float acc[4][4][4];
        #pragma unroll
        for (int mf = 0; mf < 4; ++mf)
            #pragma unroll
            for (int nf = 0; nf < 4; ++nf)
                #pragma unroll
                for (int e = 0; e < 4; ++e) acc[mf][nf][e] = 0.f;

        const uint4* Af = (const uint4*)sA + warp_m * 128;
        const uint2* Bf = (const uint2*)(sB + buf * 32768) + warp_n * 128;
        #pragma unroll
        for (int ks = 0; ks < 8; ++ks) {
            uint4 a[4]; uint2 b[4];
            #pragma unroll
            for (int mf = 0; mf < 4; ++mf) a[mf] = Af[ks * 256 + mf * 32 + lane];
            #pragma unroll
            for (int nf = 0; nf < 4; ++nf) b[nf] = Bf[ks * 512 + nf * 32 + lane];
            #pragma unroll
            for (int mf = 0; mf < 4; ++mf)
                #pragma unroll
                for (int nf = 0; nf < 4; ++nf)
                    mma_f16(acc[mf][nf], a[mf], b[nf]);
        }

        // ---- fused epilogue: row stats always, col stats if off-diagonal ----
        const float2* MB = sMB + buf * 128;
        const int jg0 = jt * 128;
        float cap[8], can[8];
        #pragma unroll
        for (int q = 0; q < 8; ++q) { cap[q] = 0.f; can[q] = 1e12f; }

        if (d != 0) {
            #pragma unroll
            for (int nf = 0; nf < 4; ++nf) {
                const int cl = warp_n * 32 + nf * 8 + (lane & 3) * 2;
                const float2 m0 = MB[cl];
                const float2 m1 = MB[cl + 1];
                #pragma unroll
                for (int mf = 0; mf < 4; ++mf)
                    #pragma unroll
                    for (int rr = 0; rr < 2; ++rr) {
                        const int r = mf * 2 + rr;
                        float2 mi = sMA[warp_m * 64 + mf * 16 + rr * 8 + (lane >> 2)];
                        float d20 = fmaf(-2.f, acc[mf][nf][rr * 2 + 0], mi.x + m0.x);
                        float d21 = fmaf(-2.f, acc[mf][nf][rr * 2 + 1], mi.x + m1.x);
                        if (mi.y == m0.y) {
                            ap[r] = fmaxf(ap[r], d20);
                            cap[nf * 2 + 0] = fmaxf(cap[nf * 2 + 0], d20);
                        } else {
                            an[r] = fminf(an[r], d20);
                            can[nf * 2 + 0] = fminf(can[nf * 2 + 0], d20);
                        }
                        if (mi.y == m1.y) {
                            ap[r] = fmaxf(ap[r], d21);
                            cap[nf * 2 + 1] = fmaxf(cap[nf * 2 + 1], d21);
                        } else {
                            an[r] = fminf(an[r], d21);
                            can[nf * 2 + 1] = fminf(can[nf * 2 + 1], d21);
                        }
                    }
            }
            // per-tile col-stat flush: reduce across lane>>2, atomics to jt rows
            #pragma unroll
            for (int q = 0; q < 8; ++q) {
                #pragma unroll
                for (int m = 4; m <= 16; m <<= 1) {
                    cap[q] = fmaxf(cap[q], __shfl_xor_sync(0xffffffffu, cap[q], m));
                    can[q] = fminf(can[q], __shfl_xor_sync(0xffffffffu, can[q], m));
                }
            }
            if (lane < 4) {
                #pragma unroll
                for (int q = 0; q < 8; ++q) {
                    int col = jg0 + warp_n * 32 + (q >> 1) * 8 + lane * 2 + (q & 1);
                    atomicMax(&g_ap[col], __float_as_uint(fmaxf(cap[q], 0.f)));
                    atomicMin(&g_an[col], __float_as_uint(fmaxf(can[q], 0.f)));
                }
            }
        } else {
            // diagonal tile: row stats only, exclude i==j
            #pragma unroll
            for (int nf = 0; nf < 4; ++nf) {
                const int cl = warp_n * 32 + nf * 8 + (lane & 3) * 2;
                const float2 m0 = MB[cl];
                const float2 m1 = MB[cl + 1];
                #pragma unroll
                for (int mf = 0; mf < 4; ++mf)
                    #pragma unroll
                    for (int rr = 0; rr < 2; ++rr) {
                        const int r = mf * 2 + rr;
                        const int ri = warp_m * 64 + mf * 16 + rr * 8 + (lane >> 2);
                        float2 mi = sMA[ri];
                        float d20 = fmaf(-2.f, acc[mf][nf][rr * 2 + 0], mi.x + m0.x);
                        float d21 = fmaf(-2.f, acc[mf][nf][rr * 2 + 1], mi.x + m1.x);
                        if (mi.y == m0.y) {
                            if (ri != cl) ap[r] = fmaxf(ap[r], d20);
                        } else an[r] = fminf(an[r], d20);
                        if (mi.y == m1.y) {
                            if (ri != cl + 1) ap[r] = fmaxf(ap[r], d21);
                        } else an[r] = fminf(an[r], d21);
                    }
            }
        }
        __syncthreads();
    }

    // ---- row-stat reduce (lanes sharing rows: xor 1,2) + atomics ----
    #pragma unroll
    for (int r = 0; r < 8; ++r) {
        ap[r] = fmaxf(ap[r], __shfl_xor_sync(0xffffffffu, ap[r], 1));
        ap[r] = fmaxf(ap[r], __shfl_xor_sync(0xffffffffu, ap[r], 2));
        an[r] = fminf(an[r], __shfl_xor_sync(0xffffffffu, an[r], 1));
        an[r] = fminf(an[r], __shfl_xor_sync(0xffffffffu, an[r], 2));
    }
    if ((lane & 3) == 0) {
        #pragma unroll
        for (int r = 0; r < 8; ++r) {
            int row = i0 + warp_m * 64 + (r >> 1) * 16 + (r & 1) * 8 + (lane >> 2);
            atomicMax(&g_ap[row], __float_as_uint(fmaxf(ap[r], 0.f)));
            atomicMin(&g_an[row], __float_as_uint(fmaxf(an[r], 0.f)));
        }
    }

    // ---- fused loss: last CTA reduces g_ap/g_an ----
    __threadfence();
    __shared__ int is_last;
    __shared__ float red[NTHR];
    if (t == 0)
        is_last = (atomicAdd(&g_done, 1) == (int)gridDim.x - 1);
    __syncthreads();
    if (is_last) {
        float s = 0.f;
        for (int i = t; i < NP; i += NTHR) {
            float apv = __uint_as_float(__ldcg(&g_ap[i]));
            float anv = __uint_as_float(__ldcg(&g_an[i]));
            float dap = sqrtf(apv);
            float dan = (anv > 9e11f) ? 1e6f : sqrtf(anv);
            s += fmaxf(0.f, 0.3f - (dan - dap));
        }
        red[t] = s;
        __syncthreads();
        #pragma unroll
        for (int m = NTHR / 2; m; m >>= 1) {
            if (t < m) red[t] += red[t + m];
            __syncthreads();
        }
        if (t == 0) {
            out[0] = red[0] * (1.0f / (float)NP);
            g_done = 0;   // reset for next graph replay
        }
    }
}

// ---------- launch ----------
extern "C" void kernel_launch(void* const* d_in, const int* in_sizes, int n_in,
                              void* d_out, int out_size) {
    const float* feat = (const float*)d_in[0];
    const int*   lab  = (const int*)d_in[1];
    float*       out  = (float*)d_out;
    (void)in_sizes; (void)n_in; (void)out_size;

    const int smem_bytes = 98304 + 1024 + 2048;   // 101376
    cudaFuncSetAttribute(triplet_mma,
                         cudaFuncAttributeMaxDynamicSharedMemorySize,
                         smem_bytes);

    prep_kernel<<<NP / 8, 256>>>(feat, lab);
    triplet_mma<<<256, NTHR, smem_bytes>>>(out);
}